// round 1
// baseline (speedup 1.0000x reference)
#include <cuda_runtime.h>
#include <cuda_bf16.h>
#include <math.h>

#define D 128
#define BATCH 16
#define NSEQ 1024
#define M_ROWS 16384
#define NE 32768
#define NS 6
#define NL 4

typedef unsigned long long u64;
typedef long long i64;

// ---------------- scratch (static device allocations are allowed) ----------
__device__ float g_q[M_ROWS * D];
__device__ float g_k[M_ROWS * D];
__device__ float g_v[M_ROWS * D];
__device__ float g_sc[(size_t)BATCH * NSEQ * NSEQ];   // 64 MB
__device__ float g_T[M_ROWS * D];
__device__ float g_Y[M_ROWS * D];
__device__ float g_Z[M_ROWS * D];

// ---------------- helpers ---------------------------------------------------
__device__ __forceinline__ void fma2(u64& d, u64 a, u64 b) {
    asm("fma.rn.f32x2 %0, %1, %2, %0;" : "+l"(d) : "l"(a), "l"(b));
}
__device__ __forceinline__ float hsum2(u64 v) {
    float2 f = *reinterpret_cast<float2*>(&v);
    return f.x + f.y;
}
__device__ __forceinline__ void red4(float* p, float a, float b, float c, float d) {
    asm volatile("red.global.add.v4.f32 [%0], {%1,%2,%3,%4};"
                 :: "l"(p), "f"(a), "f"(b), "f"(c), "f"(d) : "memory");
}

// ---------------- GEMM  C[m,n] (+)= scale * sum_d A[m,d] * B[n,d] -----------
// 128x128 tile, 256 threads, 8x8 micro-tile, f32x2 packed FMA over K pairs.
// GS=true: A rows gathered via gidx, results scatter-added via sidx (red.v4).
template<bool GS>
__global__ __launch_bounds__(256, 1)
void gemm_nt(const float* __restrict__ A, i64 aZ,
             const float* __restrict__ Bw, i64 bZ,
             float* __restrict__ C, i64 cZ, int ldc,
             const int* __restrict__ gidx, const int* __restrict__ sidx, i64 iZ,
             float scale)
{
    extern __shared__ float4 s4[];
    float4* sA = s4;            // [128 rows][32 f4], xor-swizzled
    float4* sB = s4 + 4096;

    const int z = blockIdx.z;
    const float* Ab = A + (i64)z * aZ;
    const float* Bb = Bw + (i64)z * bZ;
    float* Cb = C + (i64)z * cZ;
    const int row0 = blockIdx.x * 128;
    const int col0 = blockIdx.y * 128;
    const int tid = threadIdx.x;

    const int* gi = 0;
    const int* si = 0;
    if (GS) {
        gi = gidx + (i64)z * iZ + row0;
        si = sidx + (i64)z * iZ + row0;
    }

    #pragma unroll
    for (int i = 0; i < 16; i++) {
        int slot = tid + i * 256;
        int r = slot >> 5, c4 = slot & 31;
        int sw = c4 ^ ((r >> 3) & 7);
        i64 arow = GS ? (i64)__ldg(gi + r) : (i64)(row0 + r);
        sA[r * 32 + sw] = __ldg(reinterpret_cast<const float4*>(Ab + arow * D) + c4);
        sB[r * 32 + sw] = __ldg(reinterpret_cast<const float4*>(Bb + (i64)(col0 + r) * D) + c4);
    }
    __syncthreads();

    const int rg = tid >> 4, cg = tid & 15;
    const float4* A4 = sA + rg * 8 * 32;
    const float4* B4 = sB + cg * 8 * 32;
    const int rx = rg & 7, cx = cg & 7;

    u64 acc[8][8];
    #pragma unroll
    for (int i = 0; i < 8; i++)
        #pragma unroll
        for (int j = 0; j < 8; j++) acc[i][j] = 0ull;

    #pragma unroll 1
    for (int k4 = 0; k4 < 32; k4++) {
        u64 a0[8], a1[8], b0[8], b1[8];
        const int ka = k4 ^ rx, kb = k4 ^ cx;
        #pragma unroll
        for (int i = 0; i < 8; i++) {
            float4 t = A4[i * 32 + ka];
            a0[i] = reinterpret_cast<const u64*>(&t)[0];
            a1[i] = reinterpret_cast<const u64*>(&t)[1];
        }
        #pragma unroll
        for (int j = 0; j < 8; j++) {
            float4 t = B4[j * 32 + kb];
            b0[j] = reinterpret_cast<const u64*>(&t)[0];
            b1[j] = reinterpret_cast<const u64*>(&t)[1];
        }
        #pragma unroll
        for (int i = 0; i < 8; i++)
            #pragma unroll
            for (int j = 0; j < 8; j++) {
                fma2(acc[i][j], a0[i], b0[j]);
                fma2(acc[i][j], a1[i], b1[j]);
            }
    }

    if (GS) {
        #pragma unroll
        for (int i = 0; i < 8; i++) {
            i64 drow = (i64)si[rg * 8 + i];
            float* p = Cb + drow * D + col0 + cg * 8;
            red4(p,     hsum2(acc[i][0]), hsum2(acc[i][1]), hsum2(acc[i][2]), hsum2(acc[i][3]));
            red4(p + 4, hsum2(acc[i][4]), hsum2(acc[i][5]), hsum2(acc[i][6]), hsum2(acc[i][7]));
        }
    } else {
        #pragma unroll
        for (int i = 0; i < 8; i++) {
            float* p = Cb + (i64)(row0 + rg * 8 + i) * ldc + col0 + cg * 8;
            float4 o0 = make_float4(hsum2(acc[i][0]) * scale, hsum2(acc[i][1]) * scale,
                                    hsum2(acc[i][2]) * scale, hsum2(acc[i][3]) * scale);
            float4 o1 = make_float4(hsum2(acc[i][4]) * scale, hsum2(acc[i][5]) * scale,
                                    hsum2(acc[i][6]) * scale, hsum2(acc[i][7]) * scale);
            *reinterpret_cast<float4*>(p) = o0;
            *reinterpret_cast<float4*>(p + 4) = o1;
        }
    }
}

// -------- attention PV:  X[b,n,d] = F[b,n,d] + sum_m S[b,n,m] * V[b,m,d] ----
__global__ __launch_bounds__(256, 1)
void gemm_nn_att(const float* __restrict__ S, const float* __restrict__ V,
                 const float* __restrict__ F, float* __restrict__ X)
{
    extern __shared__ float4 s4[];
    float4* sA = s4;            // scores tile [128 n][32 m4]
    float4* sB = s4 + 4096;     // v tile [128 m][32 d4]
    const int b = blockIdx.z;
    const float* Sb = S + (i64)b * NSEQ * NSEQ;
    const float* Vb = V + (i64)b * NSEQ * D;
    const int row0 = blockIdx.x * 128;
    const int tid = threadIdx.x;
    const int rg = tid >> 4, cg = tid & 15;
    const int rx = rg & 7;
    const int cg2 = cg * 2;

    float acc[8][8];
    #pragma unroll
    for (int i = 0; i < 8; i++)
        #pragma unroll
        for (int j = 0; j < 8; j++) acc[i][j] = 0.f;

    for (int kt = 0; kt < 8; kt++) {
        #pragma unroll
        for (int i = 0; i < 16; i++) {
            int slot = tid + i * 256;
            int r = slot >> 5, c4 = slot & 31;
            int sw = c4 ^ ((r >> 3) & 7);
            sA[r * 32 + sw] = __ldg(reinterpret_cast<const float4*>(Sb + (i64)(row0 + r) * NSEQ + kt * 128) + c4);
            sB[r * 32 + sw] = __ldg(reinterpret_cast<const float4*>(Vb + (i64)(kt * 128 + r) * D) + c4);
        }
        __syncthreads();
        const float4* A4 = sA + rg * 8 * 32;
        #pragma unroll 1
        for (int k4 = 0; k4 < 32; k4++) {
            float4 a[8];
            const int ka = k4 ^ rx;
            #pragma unroll
            for (int i = 0; i < 8; i++) a[i] = A4[i * 32 + ka];
            #pragma unroll
            for (int kk = 0; kk < 4; kk++) {
                const int k = k4 * 4 + kk;
                const int kx = (k >> 3) & 7;
                const float4 bl = sB[k * 32 + (cg2 ^ kx)];
                const float4 bh = sB[k * 32 + ((cg2 + 1) ^ kx)];
                #pragma unroll
                for (int i = 0; i < 8; i++) {
                    float av = (kk == 0) ? a[i].x : (kk == 1) ? a[i].y : (kk == 2) ? a[i].z : a[i].w;
                    acc[i][0] += av * bl.x; acc[i][1] += av * bl.y;
                    acc[i][2] += av * bl.z; acc[i][3] += av * bl.w;
                    acc[i][4] += av * bh.x; acc[i][5] += av * bh.y;
                    acc[i][6] += av * bh.z; acc[i][7] += av * bh.w;
                }
            }
        }
        __syncthreads();
    }

    #pragma unroll
    for (int i = 0; i < 8; i++) {
        i64 m = (i64)b * NSEQ + row0 + rg * 8 + i;
        const float* fp = F + m * D + cg * 8;
        float* xp = X + m * D + cg * 8;
        float4 f0 = *reinterpret_cast<const float4*>(fp);
        float4 f1 = *reinterpret_cast<const float4*>(fp + 4);
        float4 o0 = make_float4(acc[i][0] + f0.x, acc[i][1] + f0.y, acc[i][2] + f0.z, acc[i][3] + f0.w);
        float4 o1 = make_float4(acc[i][4] + f1.x, acc[i][5] + f1.y, acc[i][6] + f1.z, acc[i][7] + f1.w);
        *reinterpret_cast<float4*>(xp) = o0;
        *reinterpret_cast<float4*>(xp + 4) = o1;
    }
}

// ---------------- row softmax over 1024 --------------------------------------
__global__ __launch_bounds__(256)
void softmax_k(float* __restrict__ Sc)
{
    i64 row = blockIdx.x;
    float4* p = reinterpret_cast<float4*>(Sc + row * NSEQ);
    int t = threadIdx.x;
    float4 v = p[t];
    float mx = fmaxf(fmaxf(v.x, v.y), fmaxf(v.z, v.w));
    #pragma unroll
    for (int o = 16; o; o >>= 1) mx = fmaxf(mx, __shfl_xor_sync(0xffffffffu, mx, o));
    __shared__ float red8[8];
    int w = t >> 5;
    if ((t & 31) == 0) red8[w] = mx;
    __syncthreads();
    mx = red8[0];
    #pragma unroll
    for (int i = 1; i < 8; i++) mx = fmaxf(mx, red8[i]);
    v.x = expf(v.x - mx); v.y = expf(v.y - mx);
    v.z = expf(v.z - mx); v.w = expf(v.w - mx);
    float s = v.x + v.y + v.z + v.w;
    #pragma unroll
    for (int o = 16; o; o >>= 1) s += __shfl_xor_sync(0xffffffffu, s, o);
    __syncthreads();
    if ((t & 31) == 0) red8[w] = s;
    __syncthreads();
    s = red8[0] + red8[1] + red8[2] + red8[3] + red8[4] + red8[5] + red8[6] + red8[7];
    float inv = 1.0f / s;
    v.x *= inv; v.y *= inv; v.z *= inv; v.w *= inv;
    p[t] = v;
}

// ---------------- group norm (1 group over D) + optional residual+relu ------
template<bool RES>
__global__ __launch_bounds__(128)
void gn_kernel(const float* __restrict__ in, float* __restrict__ out,
               const float* __restrict__ gw, const float* __restrict__ bw,
               const float* __restrict__ res)
{
    const i64 row = blockIdx.x;
    const int t = threadIdx.x;
    float v = in[row * D + t];
    float s1 = v, s2 = v * v;
    #pragma unroll
    for (int o = 16; o; o >>= 1) {
        s1 += __shfl_xor_sync(0xffffffffu, s1, o);
        s2 += __shfl_xor_sync(0xffffffffu, s2, o);
    }
    __shared__ float a1[4], a2[4];
    int w = t >> 5;
    if ((t & 31) == 0) { a1[w] = s1; a2[w] = s2; }
    __syncthreads();
    s1 = a1[0] + a1[1] + a1[2] + a1[3];
    s2 = a2[0] + a2[1] + a2[2] + a2[3];
    float mu = s1 * (1.0f / D);
    float var = s2 * (1.0f / D) - mu * mu;
    float y = (v - mu) * rsqrtf(var + 1e-5f) * gw[t] + bw[t];
    if (RES) y = fmaxf(y + res[row * D + t], 0.f);
    else     y = fmaxf(y, 0.f);
    out[row * D + t] = y;
}

// ---------------- driver ------------------------------------------------------
extern "C" void kernel_launch(void* const* d_in, const int* in_sizes, int n_in,
                              void* d_out, int out_size)
{
    (void)in_sizes; (void)n_in; (void)out_size;
    const float* ctrs   = (const float*)d_in[0];
    const float* feats  = (const float*)d_in[1];
    const float* Wq     = (const float*)d_in[2];
    const float* Wk     = (const float*)d_in[3];
    const float* Wv     = (const float*)d_in[4];
    const float* Wc     = (const float*)d_in[5];
    const float* Wp     = (const float*)d_in[6];
    const float* Ws     = (const float*)d_in[7];
    const float* Wl     = (const float*)d_in[8];
    const float* Wr     = (const float*)d_in[9];
    const float* Wc2    = (const float*)d_in[10];
    const float* g1     = (const float*)d_in[11];
    const float* b1     = (const float*)d_in[12];
    const float* g2     = (const float*)d_in[13];
    const float* b2     = (const float*)d_in[14];
    const int* pre_u    = (const int*)d_in[15];
    const int* pre_v    = (const int*)d_in[16];
    const int* suc_u    = (const int*)d_in[17];
    const int* suc_v    = (const int*)d_in[18];
    const int* left_u   = (const int*)d_in[19];
    const int* left_v   = (const int*)d_in[20];
    const int* right_u  = (const int*)d_in[21];
    const int* right_v  = (const int*)d_in[22];
    float* X = (float*)d_out;

    float *q, *k, *v, *sc, *T, *Y, *Z;
    cudaGetSymbolAddress((void**)&q,  g_q);
    cudaGetSymbolAddress((void**)&k,  g_k);
    cudaGetSymbolAddress((void**)&v,  g_v);
    cudaGetSymbolAddress((void**)&sc, g_sc);
    cudaGetSymbolAddress((void**)&T,  g_T);
    cudaGetSymbolAddress((void**)&Y,  g_Y);
    cudaGetSymbolAddress((void**)&Z,  g_Z);

    const int SMEM = 131072;  // 2 x 64KB tiles
    cudaFuncSetAttribute((const void*)gemm_nt<false>, cudaFuncAttributeMaxDynamicSharedMemorySize, SMEM);
    cudaFuncSetAttribute((const void*)gemm_nt<true>,  cudaFuncAttributeMaxDynamicSharedMemorySize, SMEM);
    cudaFuncSetAttribute((const void*)gemm_nn_att,    cudaFuncAttributeMaxDynamicSharedMemorySize, SMEM);

    const float NF = 0.08838834764831845f;  // 1/sqrt(128)
    dim3 blk(256);

    // ---- attention ----
    gemm_nt<false><<<dim3(128, 1, 1),  blk, SMEM>>>(ctrs,  0, Wq, 0, q,  0, D, 0, 0, 0, 1.f);
    gemm_nt<false><<<dim3(128, 1, 1),  blk, SMEM>>>(feats, 0, Wk, 0, k,  0, D, 0, 0, 0, 1.f);
    gemm_nt<false><<<dim3(128, 1, 1),  blk, SMEM>>>(feats, 0, Wv, 0, v,  0, D, 0, 0, 0, 1.f);
    gemm_nt<false><<<dim3(8, 8, 16),   blk, SMEM>>>(q, (i64)NSEQ * D, k, (i64)NSEQ * D,
                                                    sc, (i64)NSEQ * NSEQ, NSEQ, 0, 0, 0, NF);
    softmax_k<<<M_ROWS, 256>>>(sc);
    gemm_nn_att<<<dim3(8, 1, 16), blk, SMEM>>>(sc, v, feats, X);

    // ---- 4-layer fusion loop (res == feat at each iteration start) ----
    for (int i = 0; i < NL; i++) {
        gemm_nt<false><<<dim3(128, 1, 1), blk, SMEM>>>(X, 0, Wc + (i64)i * D * D, 0, T, 0, D, 0, 0, 0, 1.f);
        gemm_nt<true><<<dim3(256, 1, NS), blk, SMEM>>>(X, 0, Wp + (i64)i * NS * D * D, (i64)D * D,
                                                       T, 0, D, pre_v, pre_u, NE, 1.f);
        gemm_nt<true><<<dim3(256, 1, NS), blk, SMEM>>>(X, 0, Ws + (i64)i * NS * D * D, (i64)D * D,
                                                       T, 0, D, suc_v, suc_u, NE, 1.f);
        gemm_nt<true><<<dim3(256, 1, 1),  blk, SMEM>>>(X, 0, Wl + (i64)i * D * D, 0,
                                                       T, 0, D, left_v, left_u, 0, 1.f);
        gemm_nt<true><<<dim3(256, 1, 1),  blk, SMEM>>>(X, 0, Wr + (i64)i * D * D, 0,
                                                       T, 0, D, right_v, right_u, 0, 1.f);
        gn_kernel<false><<<M_ROWS, 128>>>(T, Y, g1 + i * D, b1 + i * D, 0);
        gemm_nt<false><<<dim3(128, 1, 1), blk, SMEM>>>(Y, 0, Wc2 + (i64)i * D * D, 0, Z, 0, D, 0, 0, 0, 1.f);
        gn_kernel<true><<<M_ROWS, 128>>>(Z, X, g2 + i * D, b2 + i * D, X);
    }
}

// round 3
// speedup vs baseline: 1.5184x; 1.5184x over previous
#include <cuda_runtime.h>
#include <cuda_bf16.h>
#include <math.h>
#include <stdint.h>

#define D 128
#define BATCH 16
#define NSEQ 1024
#define M_ROWS 16384
#define NE 32768
#define NS 6
#define NL 4

typedef unsigned long long u64;
typedef unsigned int u32;
typedef long long i64;

// ---------------- scratch ----------------------------------------------------
__device__ float g_q[M_ROWS * D];
__device__ float g_k[M_ROWS * D];
__device__ float g_v[M_ROWS * D];
__device__ float g_vt[M_ROWS * D];                    // V transposed per batch [d][j]
__device__ float g_sc[(size_t)BATCH * NSEQ * NSEQ];   // 64 MB scores
__device__ float g_T[M_ROWS * D];
__device__ float g_Y[M_ROWS * D];
__device__ float g_Z[M_ROWS * D];

// ---------------- SMEM layout (bytes) ----------------------------------------
// Operand tiles, 128 rows x 128 bf16, row pitch 272B (17 x 16B -> ldmatrix
// 8-row groups land on 8 distinct 16B bank-groups; conflict-free, no swizzle).
#define PITCH_B   272
#define TILE_B    (128 * PITCH_B)   // 34816
#define A_HI      0
#define A_LO      (TILE_B)
#define B_HI      (2 * TILE_B)
#define B_LO      (3 * TILE_B)
#define SMEM_SZ   (4 * TILE_B)      // 139264; C staging (128x132 f32) reuses this

// ---------------- PTX helpers ------------------------------------------------
__device__ __forceinline__ u32 smem_u32(const void* p) {
    u32 a;
    asm("{ .reg .u64 t; cvta.to.shared.u64 t, %1; cvt.u32.u64 %0, t; }"
        : "=r"(a) : "l"(p));
    return a;
}
__device__ __forceinline__ void ldsm4(u32* r, u32 addr) {
    asm volatile("ldmatrix.sync.aligned.m8n8.x4.shared.b16 {%0,%1,%2,%3}, [%4];"
                 : "=r"(r[0]), "=r"(r[1]), "=r"(r[2]), "=r"(r[3]) : "r"(addr));
}
__device__ __forceinline__ void mma_bf16(float* d, const u32* a, u32 b0, u32 b1) {
    asm volatile("mma.sync.aligned.m16n8k16.row.col.f32.bf16.bf16.f32 "
                 "{%0,%1,%2,%3}, {%4,%5,%6,%7}, {%8,%9}, {%0,%1,%2,%3};"
                 : "+f"(d[0]), "+f"(d[1]), "+f"(d[2]), "+f"(d[3])
                 : "r"(a[0]), "r"(a[1]), "r"(a[2]), "r"(a[3]), "r"(b0), "r"(b1));
}
__device__ __forceinline__ void red4(float* p, float a, float b, float c, float d) {
    asm volatile("red.global.add.v4.f32 [%0], {%1,%2,%3,%4};"
                 :: "l"(p), "f"(a), "f"(b), "f"(c), "f"(d) : "memory");
}

// split fp32 float4 -> packed hi bf16x2 pair + lo bf16x2 pair
__device__ __forceinline__ void split4(float4 v, uint2& hv, uint2& lv) {
    __nv_bfloat162 h0 = __floats2bfloat162_rn(v.x, v.y);
    __nv_bfloat162 h1 = __floats2bfloat162_rn(v.z, v.w);
    float2 f0 = __bfloat1622float2(h0);
    float2 f1 = __bfloat1622float2(h1);
    __nv_bfloat162 l0 = __floats2bfloat162_rn(v.x - f0.x, v.y - f0.y);
    __nv_bfloat162 l1 = __floats2bfloat162_rn(v.z - f1.x, v.w - f1.y);
    hv = make_uint2(*(u32*)&h0, *(u32*)&h1);
    lv = make_uint2(*(u32*)&l0, *(u32*)&l1);
}

// ---------------- universal HMMA GEMM ----------------------------------------
// C[m,n] (+)= scale * sum_k A[m,k] * B[n,k], K = KT*128, fp32 I/O,
// bf16 split (hi/lo) x 3 accumulation passes on tensor pipe.
// GS: A rows gathered via gidx, output scatter-added via sidx (red.v4).
// RES: C = acc + Fres, plain store.
template<bool GS, bool RES>
__global__ __launch_bounds__(256, 1)
void mma_gemm(const float* __restrict__ A, int lda, i64 aZ,
              const float* __restrict__ B, int ldb, i64 bZ,
              float* __restrict__ C, int ldc, i64 cZ,
              const float* __restrict__ Fres, i64 fZ,
              const int* __restrict__ gidx, const int* __restrict__ sidx, i64 iZ,
              float scale, int KT)
{
    extern __shared__ char sm[];
    const u32 sb = smem_u32(sm);
    const int tid = threadIdx.x;
    const int wid = tid >> 5;
    const int lane = tid & 31;

    const int z = blockIdx.z;
    const int row0 = blockIdx.x * 128;
    const int col0 = blockIdx.y * 128;
    const float* Ab = A + (i64)z * aZ;
    const float* Bb = B + (i64)z * bZ;
    float* Cb = C + (i64)z * cZ;
    const int* gi = GS ? (gidx + (i64)z * iZ + row0) : (const int*)0;
    const int* si = GS ? (sidx + (i64)z * iZ + row0) : (const int*)0;

    // warp tile: 32 (m) x 64 (n); warps arranged 4 (m) x 2 (n)
    const int m0w = (wid >> 1) * 32;
    const int n0w = (wid & 1) * 64;

    // per-lane ldmatrix address components (byte offsets within a tile)
    const u32 aoff = (u32)(m0w + (lane & 15)) * PITCH_B + (u32)(lane >> 4) * 16;
    const u32 boff = (u32)(n0w + (lane >> 4) * 8 + (lane & 7)) * PITCH_B
                   + (u32)((lane >> 3) & 1) * 16;

    float acc[2][8][4];
    #pragma unroll
    for (int mi = 0; mi < 2; mi++)
        #pragma unroll
        for (int nj = 0; nj < 8; nj++)
            #pragma unroll
            for (int e = 0; e < 4; e++) acc[mi][nj][e] = 0.f;

    for (int kt = 0; kt < KT; kt++) {
        const int kofs = kt * 128;
        // ---- load + split fp32 -> bf16 hi/lo into SMEM ----
        #pragma unroll
        for (int i = 0; i < 16; i++) {
            int slot = i * 256 + tid;
            int r = slot >> 5, c4 = slot & 31;
            u32 off = (u32)r * PITCH_B + (u32)c4 * 8;
            i64 arow = GS ? (i64)__ldg(gi + r) : (i64)(row0 + r);
            uint2 hv, lv;
            split4(__ldg(reinterpret_cast<const float4*>(Ab + arow * (i64)lda + kofs) + c4), hv, lv);
            *reinterpret_cast<uint2*>(sm + A_HI + off) = hv;
            *reinterpret_cast<uint2*>(sm + A_LO + off) = lv;
            split4(__ldg(reinterpret_cast<const float4*>(Bb + (i64)(col0 + r) * ldb + kofs) + c4), hv, lv);
            *reinterpret_cast<uint2*>(sm + B_HI + off) = hv;
            *reinterpret_cast<uint2*>(sm + B_LO + off) = lv;
        }
        __syncthreads();

        // ---- 3 passes: (Ahi,Bhi), (Ahi,Blo), (Alo,Bhi) ----
        #pragma unroll 1
        for (int pass = 0; pass < 3; pass++) {
            const u32 abase = sb + ((pass == 2) ? A_LO : A_HI) + aoff;
            const u32 bbase = sb + ((pass == 1) ? B_LO : B_HI) + boff;
            #pragma unroll
            for (int ks = 0; ks < 8; ks++) {
                u32 a[2][4], b[4][4];
                ldsm4(a[0], abase + ks * 32);
                ldsm4(a[1], abase + ks * 32 + 16 * PITCH_B);
                #pragma unroll
                for (int p = 0; p < 4; p++)
                    ldsm4(b[p], bbase + ks * 32 + p * 16 * PITCH_B);
                #pragma unroll
                for (int mi = 0; mi < 2; mi++)
                    #pragma unroll
                    for (int nj = 0; nj < 8; nj++)
                        mma_bf16(acc[mi][nj], a[mi],
                                 b[nj >> 1][(nj & 1) * 2], b[nj >> 1][(nj & 1) * 2 + 1]);
            }
        }
        __syncthreads();   // protect SMEM reuse (next kt / staging)
    }

    // ---- stage C to SMEM (pitch 132 floats), then vectorized global out ----
    float* Cs = reinterpret_cast<float*>(sm);
    const int g = lane >> 2, q2 = (lane & 3) * 2;
    #pragma unroll
    for (int mi = 0; mi < 2; mi++)
        #pragma unroll
        for (int nj = 0; nj < 8; nj++) {
            int r = m0w + mi * 16 + g;
            int c = n0w + nj * 8 + q2;
            Cs[r * 132 + c]           = acc[mi][nj][0];
            Cs[r * 132 + c + 1]       = acc[mi][nj][1];
            Cs[(r + 8) * 132 + c]     = acc[mi][nj][2];
            Cs[(r + 8) * 132 + c + 1] = acc[mi][nj][3];
        }
    __syncthreads();

    const int rr = tid >> 1, hh = tid & 1;   // 2 threads per row, 64 cols each
    const float* srow = Cs + rr * 132 + hh * 64;
    if (GS) {
        i64 drow = (i64)__ldg(si + rr);
        float* p = Cb + drow * (i64)ldc + col0 + hh * 64;
        #pragma unroll
        for (int j = 0; j < 16; j++) {
            float4 vv = *reinterpret_cast<const float4*>(srow + j * 4);
            red4(p + j * 4, vv.x, vv.y, vv.z, vv.w);
        }
    } else {
        float* p = Cb + (i64)(row0 + rr) * ldc + col0 + hh * 64;
        const float* fp = RES ? (Fres + (i64)z * fZ + (i64)(row0 + rr) * ldc + col0 + hh * 64)
                              : (const float*)0;
        #pragma unroll
        for (int j = 0; j < 16; j++) {
            float4 vv = *reinterpret_cast<const float4*>(srow + j * 4);
            vv.x *= scale; vv.y *= scale; vv.z *= scale; vv.w *= scale;
            if (RES) {
                float4 f = *reinterpret_cast<const float4*>(fp + j * 4);
                vv.x += f.x; vv.y += f.y; vv.z += f.z; vv.w += f.w;
            }
            *reinterpret_cast<float4*>(p + j * 4) = vv;
        }
    }
}

// ---------------- V transpose: vt[b][d][j] = v[b][j][d] ----------------------
__global__ __launch_bounds__(256)
void transpose_vt(const float* __restrict__ v, float* __restrict__ vt)
{
    __shared__ float ts[32][33];
    const int b = blockIdx.z;
    const int j0 = blockIdx.x * 32, d0 = blockIdx.y * 32;
    const float* vb = v + (i64)b * NSEQ * D;
    float* vtb = vt + (i64)b * D * NSEQ;
    const int tx = threadIdx.x, ty = threadIdx.y;
    #pragma unroll
    for (int i = 0; i < 32; i += 8)
        ts[ty + i][tx] = vb[(i64)(j0 + ty + i) * D + d0 + tx];
    __syncthreads();
    #pragma unroll
    for (int i = 0; i < 32; i += 8)
        vtb[(i64)(d0 + ty + i) * NSEQ + j0 + tx] = ts[tx][ty + i];
}

// ---------------- row softmax over 1024 --------------------------------------
__global__ __launch_bounds__(256)
void softmax_k(float* __restrict__ Sc)
{
    i64 row = blockIdx.x;
    float4* p = reinterpret_cast<float4*>(Sc + row * NSEQ);
    int t = threadIdx.x;
    float4 v = p[t];
    float mx = fmaxf(fmaxf(v.x, v.y), fmaxf(v.z, v.w));
    #pragma unroll
    for (int o = 16; o; o >>= 1) mx = fmaxf(mx, __shfl_xor_sync(0xffffffffu, mx, o));
    __shared__ float red8[8];
    int w = t >> 5;
    if ((t & 31) == 0) red8[w] = mx;
    __syncthreads();
    mx = red8[0];
    #pragma unroll
    for (int i = 1; i < 8; i++) mx = fmaxf(mx, red8[i]);
    v.x = expf(v.x - mx); v.y = expf(v.y - mx);
    v.z = expf(v.z - mx); v.w = expf(v.w - mx);
    float s = v.x + v.y + v.z + v.w;
    #pragma unroll
    for (int o = 16; o; o >>= 1) s += __shfl_xor_sync(0xffffffffu, s, o);
    __syncthreads();
    if ((t & 31) == 0) red8[w] = s;
    __syncthreads();
    s = red8[0] + red8[1] + red8[2] + red8[3] + red8[4] + red8[5] + red8[6] + red8[7];
    float inv = 1.0f / s;
    v.x *= inv; v.y *= inv; v.z *= inv; v.w *= inv;
    p[t] = v;
}

// ---------------- group norm + optional residual+relu ------------------------
template<bool RES>
__global__ __launch_bounds__(128)
void gn_kernel(const float* __restrict__ in, float* __restrict__ out,
               const float* __restrict__ gw, const float* __restrict__ bw,
               const float* __restrict__ res)
{
    const i64 row = blockIdx.x;
    const int t = threadIdx.x;
    float v = in[row * D + t];
    float s1 = v, s2 = v * v;
    #pragma unroll
    for (int o = 16; o; o >>= 1) {
        s1 += __shfl_xor_sync(0xffffffffu, s1, o);
        s2 += __shfl_xor_sync(0xffffffffu, s2, o);
    }
    __shared__ float a1[4], a2[4];
    int w = t >> 5;
    if ((t & 31) == 0) { a1[w] = s1; a2[w] = s2; }
    __syncthreads();
    s1 = a1[0] + a1[1] + a1[2] + a1[3];
    s2 = a2[0] + a2[1] + a2[2] + a2[3];
    float mu = s1 * (1.0f / D);
    float var = s2 * (1.0f / D) - mu * mu;
    float y = (v - mu) * rsqrtf(var + 1e-5f) * gw[t] + bw[t];
    if (RES) y = fmaxf(y + res[row * D + t], 0.f);
    else     y = fmaxf(y, 0.f);
    out[row * D + t] = y;
}

// ---------------- driver ------------------------------------------------------
extern "C" void kernel_launch(void* const* d_in, const int* in_sizes, int n_in,
                              void* d_out, int out_size)
{
    (void)in_sizes; (void)n_in; (void)out_size;
    const float* ctrs   = (const float*)d_in[0];
    const float* feats  = (const float*)d_in[1];
    const float* Wq     = (const float*)d_in[2];
    const float* Wk     = (const float*)d_in[3];
    const float* Wv     = (const float*)d_in[4];
    const float* Wc     = (const float*)d_in[5];
    const float* Wp     = (const float*)d_in[6];
    const float* Ws     = (const float*)d_in[7];
    const float* Wl     = (const float*)d_in[8];
    const float* Wr     = (const float*)d_in[9];
    const float* Wc2    = (const float*)d_in[10];
    const float* g1     = (const float*)d_in[11];
    const float* b1     = (const float*)d_in[12];
    const float* g2     = (const float*)d_in[13];
    const float* b2     = (const float*)d_in[14];
    const int* pre_u    = (const int*)d_in[15];
    const int* pre_v    = (const int*)d_in[16];
    const int* suc_u    = (const int*)d_in[17];
    const int* suc_v    = (const int*)d_in[18];
    const int* left_u   = (const int*)d_in[19];
    const int* left_v   = (const int*)d_in[20];
    const int* right_u  = (const int*)d_in[21];
    const int* right_v  = (const int*)d_in[22];
    float* X = (float*)d_out;

    float *q, *k, *v, *vt, *sc, *T, *Y, *Z;
    cudaGetSymbolAddress((void**)&q,  g_q);
    cudaGetSymbolAddress((void**)&k,  g_k);
    cudaGetSymbolAddress((void**)&v,  g_v);
    cudaGetSymbolAddress((void**)&vt, g_vt);
    cudaGetSymbolAddress((void**)&sc, g_sc);
    cudaGetSymbolAddress((void**)&T,  g_T);
    cudaGetSymbolAddress((void**)&Y,  g_Y);
    cudaGetSymbolAddress((void**)&Z,  g_Z);

    cudaFuncSetAttribute((const void*)mma_gemm<false,false>, cudaFuncAttributeMaxDynamicSharedMemorySize, SMEM_SZ);
    cudaFuncSetAttribute((const void*)mma_gemm<true, false>, cudaFuncAttributeMaxDynamicSharedMemorySize, SMEM_SZ);
    cudaFuncSetAttribute((const void*)mma_gemm<false,true >, cudaFuncAttributeMaxDynamicSharedMemorySize, SMEM_SZ);

    const float NF = 0.08838834764831845f;  // 1/sqrt(128)
    dim3 blk(256);

    // ---- attention ----
    mma_gemm<false,false><<<dim3(128,1,1), blk, SMEM_SZ>>>(ctrs,  D, 0, Wq, D, 0, q, D, 0, 0, 0, 0, 0, 0, 1.f, 1);
    mma_gemm<false,false><<<dim3(128,1,1), blk, SMEM_SZ>>>(feats, D, 0, Wk, D, 0, k, D, 0, 0, 0, 0, 0, 0, 1.f, 1);
    mma_gemm<false,false><<<dim3(128,1,1), blk, SMEM_SZ>>>(feats, D, 0, Wv, D, 0, v, D, 0, 0, 0, 0, 0, 0, 1.f, 1);
    transpose_vt<<<dim3(NSEQ/32, D/32, BATCH), dim3(32,8)>>>(v, vt);
    mma_gemm<false,false><<<dim3(8,8,16), blk, SMEM_SZ>>>(q, D, (i64)NSEQ*D, k, D, (i64)NSEQ*D,
                                                          sc, NSEQ, (i64)NSEQ*NSEQ, 0, 0, 0, 0, 0, NF, 1);
    softmax_k<<<M_ROWS, 256>>>(sc);
    mma_gemm<false,true><<<dim3(8,1,16), blk, SMEM_SZ>>>(sc, NSEQ, (i64)NSEQ*NSEQ, vt, NSEQ, (i64)D*NSEQ,
                                                         X, D, (i64)NSEQ*D, feats, (i64)NSEQ*D, 0, 0, 0, 1.f, 8);

    // ---- 4-layer fusion loop ----
    for (int i = 0; i < NL; i++) {
        mma_gemm<false,false><<<dim3(128,1,1), blk, SMEM_SZ>>>(X, D, 0, Wc + (i64)i*D*D, D, 0,
                                                               T, D, 0, 0, 0, 0, 0, 0, 1.f, 1);
        mma_gemm<true,false><<<dim3(256,1,NS), blk, SMEM_SZ>>>(X, D, 0, Wp + (i64)i*NS*D*D, D, (i64)D*D,
                                                               T, D, 0, 0, 0, pre_v, pre_u, NE, 1.f, 1);
        mma_gemm<true,false><<<dim3(256,1,NS), blk, SMEM_SZ>>>(X, D, 0, Ws + (i64)i*NS*D*D, D, (i64)D*D,
                                                               T, D, 0, 0, 0, suc_v, suc_u, NE, 1.f, 1);
        mma_gemm<true,false><<<dim3(256,1,1),  blk, SMEM_SZ>>>(X, D, 0, Wl + (i64)i*D*D, D, 0,
                                                               T, D, 0, 0, 0, left_v, left_u, 0, 1.f, 1);
        mma_gemm<true,false><<<dim3(256,1,1),  blk, SMEM_SZ>>>(X, D, 0, Wr + (i64)i*D*D, D, 0,
                                                               T, D, 0, 0, 0, right_v, right_u, 0, 1.f, 1);
        gn_kernel<false><<<M_ROWS, 128>>>(T, Y, g1 + i*D, b1 + i*D, 0);
        mma_gemm<false,false><<<dim3(128,1,1), blk, SMEM_SZ>>>(Y, D, 0, Wc2 + (i64)i*D*D, D, 0,
                                                               Z, D, 0, 0, 0, 0, 0, 0, 1.f, 1);
        gn_kernel<true><<<M_ROWS, 128>>>(Z, X, g2 + i*D, b2 + i*D, X);
    }
}